// round 11
// baseline (speedup 1.0000x reference)
#include <cuda_runtime.h>
#include <cuda_fp16.h>
#include <cstdint>
#include <cstddef>

// ---------------------------------------------------------------------------
// Problem constants
// ---------------------------------------------------------------------------
#define B_SZ   8192
#define D_SZ   8
#define P_SZ   10
#define R_SZ   512
#define OUT_SZ 64
#define NMID   6
#define KTOT   (P_SZ * R_SZ)   // 5120
#define KC     32              // K per pipeline chunk
#define RCH    (R_SZ / KC)     // 16 chunks per j
#define NCH    (KTOT / KC)     // 160

// ---------------------------------------------------------------------------
// Device-global scratch
// ---------------------------------------------------------------------------
__device__ float  g_tanh_g0[P_SZ * R_SZ];
__device__ float  g_resf[(size_t)B_SZ * R_SZ];    // f32 master res between layers
__device__ __half g_qa_hi[(size_t)B_SZ * R_SZ];   // fp16 hi of res/s
__device__ __half g_qa_lo[(size_t)B_SZ * R_SZ];   // fp16 lo of res/s
__device__ float  g_sa[B_SZ];                     // per-row scale
// B operands: tanh'd, transposed to [n][k=j*512+r], SINGLE fp16 (|tanh|<=0.1)
__device__ __half g_b_mid[(size_t)NMID * R_SZ * KTOT];
__device__ __half g_b_last[(size_t)OUT_SZ * KTOT];

// ---------------------------------------------------------------------------
// PTX helpers (sm_80-era: cp.async, ldmatrix, mma.sync — NO tcgen05)
// ---------------------------------------------------------------------------
__device__ __forceinline__ uint32_t smem_u32(const void* p) {
    uint32_t a;
    asm("{ .reg .u64 t; cvta.to.shared.u64 t, %1; cvt.u32.u64 %0, t; }" : "=r"(a) : "l"(p));
    return a;
}
#define CP_ASYNC16(dst, src) \
    asm volatile("cp.async.cg.shared.global [%0], [%1], 16;" :: "r"(dst), "l"(src) : "memory")
#define CP_COMMIT() asm volatile("cp.async.commit_group;" ::: "memory")
#define CP_WAIT3()  asm volatile("cp.async.wait_group 3;" ::: "memory")
#define CP_WAIT2()  asm volatile("cp.async.wait_group 2;" ::: "memory")

#define LDSM4(r0, r1, r2, r3, addr) \
    asm volatile("ldmatrix.sync.aligned.m8n8.x4.shared.b16 {%0,%1,%2,%3}, [%4];" \
                 : "=r"(r0), "=r"(r1), "=r"(r2), "=r"(r3) : "r"(addr))

#define MMA_F16(d, a, b) \
    asm volatile("mma.sync.aligned.m16n8k16.row.col.f32.f16.f16.f32 " \
                 "{%0,%1,%2,%3}, {%4,%5,%6,%7}, {%8,%9}, {%0,%1,%2,%3};" \
                 : "+f"((d)[0]), "+f"((d)[1]), "+f"((d)[2]), "+f"((d)[3]) \
                 : "r"((a)[0]), "r"((a)[1]), "r"((a)[2]), "r"((a)[3]), \
                   "r"((b)[0]), "r"((b)[1]))

// 64B-row XOR swizzle: conflict-free across all 8-row ldmatrix phases.
__device__ __forceinline__ uint32_t sw64(uint32_t row, uint32_t c16) {
    return row * 64u + ((c16 ^ ((row >> 1) & 3u)) << 4);
}

// ---------------------------------------------------------------------------
// Precompute: tanh + transpose -> single fp16
// ---------------------------------------------------------------------------
__global__ void trans_f16_kernel(const float* __restrict__ G,
                                 __half* __restrict__ bo,
                                 int N, size_t gStride, size_t oStride) {
    __shared__ float t[32][33];
    int layer = blockIdx.z / P_SZ;
    int j     = blockIdx.z % P_SZ;
    const float* Gp = G + (size_t)layer * gStride;
    __half* bop = bo + (size_t)layer * oStride;
    int rt = blockIdx.x * 32, nt = blockIdx.y * 32;
    int tx = threadIdx.x, ty = threadIdx.y;
#pragma unroll
    for (int yy = ty; yy < 32; yy += 8)
        t[yy][tx] = tanhf(Gp[((size_t)(rt + yy) * P_SZ + j) * N + nt + tx]);
    __syncthreads();
#pragma unroll
    for (int yy = ty; yy < 32; yy += 8) {
        int n = nt + yy, r = rt + tx;
        bop[(size_t)n * KTOT + (size_t)j * R_SZ + r] = __float2half_rn(t[tx][yy]);
    }
}

__global__ void tanh_small_kernel(const float* __restrict__ src,
                                  float* __restrict__ dst, int n) {
    int i = blockIdx.x * blockDim.x + threadIdx.x;
    if (i < n) dst[i] = tanhf(src[i]);
}

__global__ void first_core_kernel(const float* __restrict__ z,
                                  float* __restrict__ resf) {
    int b = blockIdx.x;
    int r = threadIdx.x;
    float zv = z[b * D_SZ + 0];
    float ph = 1.f, acc = 0.f;
#pragma unroll
    for (int j = 0; j < P_SZ; j++) {
        acc += g_tanh_g0[j * R_SZ + r] * ph;
        ph *= zv;
    }
    resf[(size_t)b * R_SZ + r] = acc;
}

// Per-row quantize: s = rowmax |x|; A_hi = fp16(x/s), A_lo = fp16(x/s - hi)
__global__ void quant_res_kernel(const float* __restrict__ resf,
                                 __half* __restrict__ qh, __half* __restrict__ ql,
                                 float* __restrict__ sa) {
    __shared__ float wmax[16];
    int b = blockIdx.x, tid = threadIdx.x;   // 512 threads
    float x = resf[(size_t)b * R_SZ + tid];
    float a = fabsf(x);
#pragma unroll
    for (int o = 16; o; o >>= 1) a = fmaxf(a, __shfl_xor_sync(0xffffffffu, a, o));
    if ((tid & 31) == 0) wmax[tid >> 5] = a;
    __syncthreads();
    if (tid < 32) {
        float m = (tid < 16) ? wmax[tid] : 0.f;
#pragma unroll
        for (int o = 8; o; o >>= 1) m = fmaxf(m, __shfl_xor_sync(0xffffffffu, m, o));
        if (tid == 0) wmax[0] = m;
    }
    __syncthreads();
    float s = fmaxf(wmax[0], 1e-30f);
    float inv = 1.0f / s;
    float q = x * inv;
    __half h = __float2half_rn(q);
    qh[(size_t)b * R_SZ + tid] = h;
    ql[(size_t)b * R_SZ + tid] = __float2half_rn(q - __half2float(h));
    if (tid == 0) sa[b] = s;
}

// ---------------------------------------------------------------------------
// MID kernel: fp16 2-pass GEMM, A (hi+lo) FULLY CACHED in smem across j-loop.
//   BM=64, BN=256, 256 threads (warp grid 2x4, warp tile 32x64).
//   Only B is streamed (5-stage cp.async ring). Horner j-descending.
//   out[m,n] = sA[m] * sum_{j desc}( acc*z + sum_r (Ah+Al)[m,r] B_j[r,n] )
// ---------------------------------------------------------------------------
__global__ void __launch_bounds__(256, 1)
tt_mma_cached(const __half* __restrict__ Ahi,
              const __half* __restrict__ Alo,
              const __half* __restrict__ Bop,
              const float* __restrict__ sa,
              const float* __restrict__ z, int zcol,
              float* __restrict__ outF) {
    constexpr int BM = 64, BN = 256;
    constexpr int MT = 2, NT = 8;          // warp tile 32x64
    constexpr int A_CH = BM * 64;          // 4KB per rc chunk-block per array
    constexpr int A_ARR = 16 * A_CH;       // 64KB per array
    constexpr int B_T = BN * 64;           // 16KB per B stage
    constexpr int NSTB = 5;

    extern __shared__ __align__(16) char sm[];
    const uint32_t base = smem_u32(sm);
    const uint32_t AHI = base;
    const uint32_t ALO = base + A_ARR;
    const uint32_t BB  = base + 2 * A_ARR;

    const int tid = threadIdx.x, lane = tid & 31, wid = tid >> 5;
    const int m0 = blockIdx.y * BM, n0 = blockIdx.x * BN;
    const int wm0 = (wid >> 2) * 32;
    const int wn0 = (wid & 3) * 64;

    // per-lane z + scale
    float zA[MT], zB[MT], sAr[MT], sBr[MT];
#pragma unroll
    for (int mt = 0; mt < MT; mt++) {
        int rA = m0 + wm0 + mt * 16 + (lane >> 2);
        zA[mt] = z[(size_t)rA * D_SZ + zcol];
        zB[mt] = z[(size_t)(rA + 8) * D_SZ + zcol];
        sAr[mt] = sa[rA];
        sBr[mt] = sa[rA + 8];
    }

    float acc[MT][NT][4];
#pragma unroll
    for (int mt = 0; mt < MT; mt++)
#pragma unroll
        for (int nt = 0; nt < NT; nt++)
#pragma unroll
            for (int q = 0; q < 4; q++) acc[mt][nt][q] = 0.f;

    // ---- prologue: load entire A slice (hi+lo) into smem, one commit group ----
#pragma unroll
    for (int i = 0; i < 16; i++) {
        const int idx = tid + i * 256;
        const int rc = idx >> 8, rem = idx & 255;
        const int row = rem >> 2, c16 = rem & 3;
        const uint32_t off = rc * A_CH + sw64(row, c16);
        const size_t go = (size_t)(m0 + row) * R_SZ + rc * KC + c16 * 8;
        CP_ASYNC16(AHI + off, Ahi + go);
        CP_ASYNC16(ALO + off, Alo + go);
    }
    CP_COMMIT();

    // B producer (one stage per call, own commit group)
    auto produceB = [&](int cc) {
        const int s = cc % NSTB;
        const int j = (P_SZ - 1) - (cc >> 4);
        const int rr = cc & 15;
        const uint32_t bS = BB + s * B_T;
#pragma unroll
        for (int i = 0; i < 4; i++) {
            const int idx = tid + i * 256;
            const int row = idx >> 2, c16 = idx & 3;
            const size_t go = (size_t)(n0 + row) * KTOT + j * R_SZ + rr * KC + c16 * 8;
            CP_ASYNC16(bS + sw64(row, c16), Bop + go);
        }
        CP_COMMIT();
    };

    produceB(0); produceB(1); produceB(2); produceB(3);

    auto mma_chunk = [&](int rc, int s) {
        const uint32_t aH = AHI + rc * A_CH;
        const uint32_t aL = ALO + rc * A_CH;
        const uint32_t bS = BB + s * B_T;
#pragma unroll
        for (int ks = 0; ks < 2; ks++) {
            uint32_t b[NT][2];
#pragma unroll
            for (int n2 = 0; n2 < NT / 2; n2++) {
                const uint32_t rowb = wn0 + n2 * 16 + ((lane >> 4) << 3) + (lane & 7);
                const uint32_t c16b = ((lane >> 3) & 1) + 2 * ks;
                LDSM4(b[2 * n2][0], b[2 * n2][1], b[2 * n2 + 1][0], b[2 * n2 + 1][1],
                      bS + sw64(rowb, c16b));
            }
            uint32_t a[MT][4];
#pragma unroll
            for (int mt = 0; mt < MT; mt++) {
                const uint32_t rowa = wm0 + mt * 16 + (lane & 15);
                LDSM4(a[mt][0], a[mt][1], a[mt][2], a[mt][3],
                      aH + sw64(rowa, (lane >> 4) + 2 * ks));
            }
#pragma unroll
            for (int mt = 0; mt < MT; mt++)
#pragma unroll
                for (int nt = 0; nt < NT; nt++) MMA_F16(acc[mt][nt], a[mt], b[nt]);
#pragma unroll
            for (int mt = 0; mt < MT; mt++) {
                const uint32_t rowa = wm0 + mt * 16 + (lane & 15);
                LDSM4(a[mt][0], a[mt][1], a[mt][2], a[mt][3],
                      aL + sw64(rowa, (lane >> 4) + 2 * ks));
            }
#pragma unroll
            for (int mt = 0; mt < MT; mt++)
#pragma unroll
                for (int nt = 0; nt < NT; nt++) MMA_F16(acc[mt][nt], a[mt], b[nt]);
        }
    };

    for (int c = 0; c < NCH; c++) {
        CP_WAIT3();            // A group + B_c complete (<=3 younger outstanding)
        __syncthreads();
        if (c + 4 < NCH) produceB(c + 4); else CP_COMMIT();
        if (c && (c & 15) == 0) {
            // Horner: entering next-lower j — scale accumulators by z
#pragma unroll
            for (int mt = 0; mt < MT; mt++)
#pragma unroll
                for (int nt = 0; nt < NT; nt++) {
                    acc[mt][nt][0] *= zA[mt]; acc[mt][nt][1] *= zA[mt];
                    acc[mt][nt][2] *= zB[mt]; acc[mt][nt][3] *= zB[mt];
                }
        }
        mma_chunk(c & 15, c % NSTB);
    }

    // epilogue: apply per-row scale, write f32
#pragma unroll
    for (int mt = 0; mt < MT; mt++) {
        const int row0 = m0 + wm0 + mt * 16 + (lane >> 2);
#pragma unroll
        for (int nt = 0; nt < NT; nt++) {
            const int col = n0 + wn0 + nt * 8 + (lane & 3) * 2;
            *reinterpret_cast<float2*>(&outF[(size_t)row0 * R_SZ + col]) =
                make_float2(acc[mt][nt][0] * sAr[mt], acc[mt][nt][1] * sAr[mt]);
            *reinterpret_cast<float2*>(&outF[(size_t)(row0 + 8) * R_SZ + col]) =
                make_float2(acc[mt][nt][2] * sBr[mt], acc[mt][nt][3] * sBr[mt]);
        }
    }
}

// ---------------------------------------------------------------------------
// LAST kernel: small streaming 2-pass GEMM (64x64), as in R10.
// ---------------------------------------------------------------------------
__global__ void __launch_bounds__(256, 1)
tt_mma_last(const __half* __restrict__ Ahi,
            const __half* __restrict__ Alo,
            const __half* __restrict__ Bop,
            const float* __restrict__ sa,
            const float* __restrict__ z, int zcol,
            float* __restrict__ outF, int Ntotal) {
    constexpr int BM = 64, BN = 64, MT = 2, NT = 2;   // warp tile 32x16, 8 warps (2x4)
    constexpr int A_T = BM * 64;
    constexpr int B_T = BN * 64;
    constexpr int STAGE = 2 * A_T + B_T;
    constexpr int NSTAGE = 4;

    extern __shared__ __align__(16) char sm[];
    const uint32_t base = smem_u32(sm);

    const int tid = threadIdx.x, lane = tid & 31, wid = tid >> 5;
    const int m0 = blockIdx.y * BM, n0 = blockIdx.x * BN;
    const int wm0 = (wid >> 2) * 32;
    const int wn0 = (wid & 3) * 16;

    float zA[MT], zB[MT], sAr[MT], sBr[MT];
#pragma unroll
    for (int mt = 0; mt < MT; mt++) {
        int rA = m0 + wm0 + mt * 16 + (lane >> 2);
        zA[mt] = z[(size_t)rA * D_SZ + zcol];
        zB[mt] = z[(size_t)(rA + 8) * D_SZ + zcol];
        sAr[mt] = sa[rA];
        sBr[mt] = sa[rA + 8];
    }

    float acc[MT][NT][4];
#pragma unroll
    for (int mt = 0; mt < MT; mt++)
#pragma unroll
        for (int nt = 0; nt < NT; nt++)
#pragma unroll
            for (int q = 0; q < 4; q++) acc[mt][nt][q] = 0.f;

    auto produce = [&](int cc) {
        const int s = cc & (NSTAGE - 1);
        const int j = (P_SZ - 1) - cc / RCH;
        const int rr = cc & (RCH - 1);
        const uint32_t aH = base + s * STAGE;
        const uint32_t aL = aH + A_T;
        const uint32_t bS = aH + 2 * A_T;
        {
            const int idx = tid;                 // 256 = BM*4
            const int row = idx >> 2, c16 = idx & 3;
            const uint32_t off = sw64(row, c16);
            const size_t go = (size_t)(m0 + row) * R_SZ + rr * KC + c16 * 8;
            CP_ASYNC16(aH + off, Ahi + go);
            CP_ASYNC16(aL + off, Alo + go);
            const size_t gb = (size_t)(n0 + row) * KTOT + j * R_SZ + rr * KC + c16 * 8;
            CP_ASYNC16(bS + off, Bop + gb);
        }
        CP_COMMIT();
    };

    auto mma_chunk = [&](int s) {
        const uint32_t aH = base + s * STAGE;
        const uint32_t aL = aH + A_T;
        const uint32_t bS = aH + 2 * A_T;
#pragma unroll
        for (int ks = 0; ks < 2; ks++) {
            uint32_t b[NT][2];
            {
                const uint32_t rowb = wn0 + ((lane >> 4) << 3) + (lane & 7);
                const uint32_t c16b = ((lane >> 3) & 1) + 2 * ks;
                LDSM4(b[0][0], b[0][1], b[1][0], b[1][1], bS + sw64(rowb, c16b));
            }
            uint32_t a[MT][4];
#pragma unroll
            for (int mt = 0; mt < MT; mt++) {
                const uint32_t rowa = wm0 + mt * 16 + (lane & 15);
                LDSM4(a[mt][0], a[mt][1], a[mt][2], a[mt][3],
                      aH + sw64(rowa, (lane >> 4) + 2 * ks));
            }
#pragma unroll
            for (int mt = 0; mt < MT; mt++)
#pragma unroll
                for (int nt = 0; nt < NT; nt++) MMA_F16(acc[mt][nt], a[mt], b[nt]);
#pragma unroll
            for (int mt = 0; mt < MT; mt++) {
                const uint32_t rowa = wm0 + mt * 16 + (lane & 15);
                LDSM4(a[mt][0], a[mt][1], a[mt][2], a[mt][3],
                      aL + sw64(rowa, (lane >> 4) + 2 * ks));
            }
#pragma unroll
            for (int mt = 0; mt < MT; mt++)
#pragma unroll
                for (int nt = 0; nt < NT; nt++) MMA_F16(acc[mt][nt], a[mt], b[nt]);
        }
    };

    produce(0); produce(1); produce(2);

    for (int c = 0; c < NCH; c++) {
        CP_WAIT2();
        __syncthreads();
        if (c + 3 < NCH) produce(c + 3); else CP_COMMIT();
        if (c && (c & (RCH - 1)) == 0) {
#pragma unroll
            for (int mt = 0; mt < MT; mt++)
#pragma unroll
                for (int nt = 0; nt < NT; nt++) {
                    acc[mt][nt][0] *= zA[mt]; acc[mt][nt][1] *= zA[mt];
                    acc[mt][nt][2] *= zB[mt]; acc[mt][nt][3] *= zB[mt];
                }
        }
        mma_chunk(c & (NSTAGE - 1));
    }

#pragma unroll
    for (int mt = 0; mt < MT; mt++) {
        const int row0 = m0 + wm0 + mt * 16 + (lane >> 2);
#pragma unroll
        for (int nt = 0; nt < NT; nt++) {
            const int col = n0 + wn0 + nt * 8 + (lane & 3) * 2;
            *reinterpret_cast<float2*>(&outF[(size_t)row0 * Ntotal + col]) =
                make_float2(acc[mt][nt][0] * sAr[mt], acc[mt][nt][1] * sAr[mt]);
            *reinterpret_cast<float2*>(&outF[(size_t)(row0 + 8) * Ntotal + col]) =
                make_float2(acc[mt][nt][2] * sBr[mt], acc[mt][nt][3] * sBr[mt]);
        }
    }
}

// ---------------------------------------------------------------------------
// Launch (graph-capturable, allocation-free)
// ---------------------------------------------------------------------------
extern "C" void kernel_launch(void* const* d_in, const int* in_sizes, int n_in,
                              void* d_out, int out_size) {
    (void)in_sizes; (void)n_in; (void)out_size;
    const float* z     = (const float*)d_in[0];
    const float* G0    = (const float*)d_in[1];
    const float* Gmid  = (const float*)d_in[2];
    const float* Glast = (const float*)d_in[3];
    float* out = (float*)d_out;

    float *p_tg0, *p_resf, *p_sa;
    __half *p_qah, *p_qal, *p_bm, *p_bl;
    cudaGetSymbolAddress((void**)&p_tg0,  g_tanh_g0);
    cudaGetSymbolAddress((void**)&p_resf, g_resf);
    cudaGetSymbolAddress((void**)&p_sa,   g_sa);
    cudaGetSymbolAddress((void**)&p_qah,  g_qa_hi);
    cudaGetSymbolAddress((void**)&p_qal,  g_qa_lo);
    cudaGetSymbolAddress((void**)&p_bm,   g_b_mid);
    cudaGetSymbolAddress((void**)&p_bl,   g_b_last);

    const int SMEM_MID  = 2 * 16 * 64 * 64 + 5 * 256 * 64;   // 131072 + 81920 = 212992
    const int SMEM_LAST = 4 * (2 * 64 + 64) * 64;            // 49152
    cudaFuncSetAttribute((const void*)tt_mma_cached,
                         cudaFuncAttributeMaxDynamicSharedMemorySize, SMEM_MID);
    cudaFuncSetAttribute((const void*)tt_mma_last,
                         cudaFuncAttributeMaxDynamicSharedMemorySize, SMEM_LAST);

    // precompute
    tanh_small_kernel<<<(P_SZ * R_SZ + 255) / 256, 256>>>(G0, p_tg0, P_SZ * R_SZ);
    trans_f16_kernel<<<dim3(R_SZ / 32, R_SZ / 32, NMID * P_SZ), dim3(32, 8)>>>(
        Gmid, p_bm, R_SZ, (size_t)R_SZ * P_SZ * R_SZ, (size_t)R_SZ * KTOT);
    trans_f16_kernel<<<dim3(R_SZ / 32, OUT_SZ / 32, P_SZ), dim3(32, 8)>>>(
        Glast, p_bl, OUT_SZ, 0, 0);

    // first core -> f32 res -> quantize
    first_core_kernel<<<B_SZ, R_SZ>>>(z, p_resf);
    quant_res_kernel<<<B_SZ, R_SZ>>>(p_resf, p_qah, p_qal, p_sa);

    // six middle cores: cached-A GEMM (f32 out) + per-row quantize
    for (int i = 0; i < NMID; i++) {
        tt_mma_cached<<<dim3(R_SZ / 256, B_SZ / 64), 256, SMEM_MID>>>(
            p_qah, p_qal, p_bm + (size_t)i * R_SZ * KTOT, p_sa,
            z, i + 1, p_resf);
        quant_res_kernel<<<B_SZ, R_SZ>>>(p_resf, p_qah, p_qal, p_sa);
    }

    // last core -> d_out [B, OUT] f32
    tt_mma_last<<<dim3(1, B_SZ / 64), 256, SMEM_LAST>>>(
        p_qah, p_qal, p_bl, p_sa, z, D_SZ - 1, out, OUT_SZ);
}

// round 12
// speedup vs baseline: 1.7533x; 1.7533x over previous
#include <cuda_runtime.h>
#include <cuda_fp16.h>
#include <cstdint>
#include <cstddef>

// ---------------------------------------------------------------------------
// Problem constants
// ---------------------------------------------------------------------------
#define B_SZ   8192
#define D_SZ   8
#define P_SZ   10
#define R_SZ   512
#define OUT_SZ 64
#define NMID   6
#define KTOT   (P_SZ * R_SZ)   // 5120
#define KC     32              // K per pipeline chunk
#define RCH    (R_SZ / KC)     // 16 chunks per j
#define NCH    (KTOT / KC)     // 160

// ---------------------------------------------------------------------------
// Device-global scratch
// ---------------------------------------------------------------------------
__device__ float  g_tanh_g0[P_SZ * R_SZ];
__device__ float  g_resf[(size_t)B_SZ * R_SZ];    // f32 master res between layers
__device__ __half g_qa[(size_t)B_SZ * R_SZ];      // fp16 of res/s (per-row scaled)
__device__ float  g_sa[B_SZ];                     // per-row scale
// B operands: tanh'd, transposed to [n][k=j*512+r], single fp16 (|tanh|<=0.1)
__device__ __half g_b_mid[(size_t)NMID * R_SZ * KTOT];
__device__ __half g_b_last[(size_t)OUT_SZ * KTOT];

// ---------------------------------------------------------------------------
// PTX helpers (sm_80-era: cp.async, ldmatrix, mma.sync — NO tcgen05)
// ---------------------------------------------------------------------------
__device__ __forceinline__ uint32_t smem_u32(const void* p) {
    uint32_t a;
    asm("{ .reg .u64 t; cvta.to.shared.u64 t, %1; cvt.u32.u64 %0, t; }" : "=r"(a) : "l"(p));
    return a;
}
#define CP_ASYNC16(dst, src) \
    asm volatile("cp.async.cg.shared.global [%0], [%1], 16;" :: "r"(dst), "l"(src) : "memory")
#define CP_COMMIT() asm volatile("cp.async.commit_group;" ::: "memory")
#define CP_WAIT2()  asm volatile("cp.async.wait_group 2;" ::: "memory")

#define LDSM4(r0, r1, r2, r3, addr) \
    asm volatile("ldmatrix.sync.aligned.m8n8.x4.shared.b16 {%0,%1,%2,%3}, [%4];" \
                 : "=r"(r0), "=r"(r1), "=r"(r2), "=r"(r3) : "r"(addr))

#define MMA_F16(d, a, b) \
    asm volatile("mma.sync.aligned.m16n8k16.row.col.f32.f16.f16.f32 " \
                 "{%0,%1,%2,%3}, {%4,%5,%6,%7}, {%8,%9}, {%0,%1,%2,%3};" \
                 : "+f"((d)[0]), "+f"((d)[1]), "+f"((d)[2]), "+f"((d)[3]) \
                 : "r"((a)[0]), "r"((a)[1]), "r"((a)[2]), "r"((a)[3]), \
                   "r"((b)[0]), "r"((b)[1]))

// 64B-row XOR swizzle: conflict-free across all 8-row ldmatrix phases.
__device__ __forceinline__ uint32_t sw64(uint32_t row, uint32_t c16) {
    return row * 64u + ((c16 ^ ((row >> 1) & 3u)) << 4);
}

// ---------------------------------------------------------------------------
// Precompute: tanh + transpose -> single fp16
//   G [R, P, N] (n contiguous) -> B [n][j*512 + r] (k contiguous)
// ---------------------------------------------------------------------------
__global__ void trans_f16_kernel(const float* __restrict__ G,
                                 __half* __restrict__ bo,
                                 int N, size_t gStride, size_t oStride) {
    __shared__ float t[32][33];
    int layer = blockIdx.z / P_SZ;
    int j     = blockIdx.z % P_SZ;
    const float* Gp = G + (size_t)layer * gStride;
    __half* bop = bo + (size_t)layer * oStride;
    int rt = blockIdx.x * 32, nt = blockIdx.y * 32;
    int tx = threadIdx.x, ty = threadIdx.y;   // block (32, 8)
#pragma unroll
    for (int yy = ty; yy < 32; yy += 8)
        t[yy][tx] = tanhf(Gp[((size_t)(rt + yy) * P_SZ + j) * N + nt + tx]);
    __syncthreads();
#pragma unroll
    for (int yy = ty; yy < 32; yy += 8) {
        int n = nt + yy, r = rt + tx;
        bop[(size_t)n * KTOT + (size_t)j * R_SZ + r] = __float2half_rn(t[tx][yy]);
    }
}

__global__ void tanh_small_kernel(const float* __restrict__ src,
                                  float* __restrict__ dst, int n) {
    int i = blockIdx.x * blockDim.x + threadIdx.x;
    if (i < n) dst[i] = tanhf(src[i]);
}

// First core -> f32 res
__global__ void first_core_kernel(const float* __restrict__ z,
                                  float* __restrict__ resf) {
    int b = blockIdx.x;
    int r = threadIdx.x;
    float zv = z[b * D_SZ + 0];
    float ph = 1.f, acc = 0.f;
#pragma unroll
    for (int j = 0; j < P_SZ; j++) {
        acc += g_tanh_g0[j * R_SZ + r] * ph;
        ph *= zv;
    }
    resf[(size_t)b * R_SZ + r] = acc;
}

// Per-row quantize: s = rowmax |x|; A = fp16(x/s)
__global__ void quant_res_kernel(const float* __restrict__ resf,
                                 __half* __restrict__ qa,
                                 float* __restrict__ sa) {
    __shared__ float wmax[16];
    int b = blockIdx.x, tid = threadIdx.x;   // 512 threads
    float x = resf[(size_t)b * R_SZ + tid];
    float a = fabsf(x);
#pragma unroll
    for (int o = 16; o; o >>= 1) a = fmaxf(a, __shfl_xor_sync(0xffffffffu, a, o));
    if ((tid & 31) == 0) wmax[tid >> 5] = a;
    __syncthreads();
    if (tid < 32) {
        float m = (tid < 16) ? wmax[tid] : 0.f;
#pragma unroll
        for (int o = 8; o; o >>= 1) m = fmaxf(m, __shfl_xor_sync(0xffffffffu, m, o));
        if (tid == 0) wmax[0] = m;
    }
    __syncthreads();
    float s = fmaxf(wmax[0], 1e-30f);
    qa[(size_t)b * R_SZ + tid] = __float2half_rn(x / s);
    if (tid == 0) sa[b] = s;
}

// ---------------------------------------------------------------------------
// HMMA fp16 SINGLE-pass GEMM with Horner phi folding + per-row scale:
//   out[m,n] = sA[m] * sum_{j desc} ( acc*z_m + sum_r A[m,r] B_j[r,n] )
// THREADS threads; warp grid (BM/WM) x (BN/WN); 4-stage cp.async pipeline.
// Epilogue writes f32 (next layer's quantizer reads it; last layer -> d_out).
// ---------------------------------------------------------------------------
template<int BM, int BN, int WM, int WN, int THREADS>
__global__ void __launch_bounds__(THREADS, 1)
tt_mma_kernel(const __half* __restrict__ Aop,
              const __half* __restrict__ Bop,
              const float* __restrict__ sa,
              const float* __restrict__ z, int zcol,
              float* __restrict__ outF, int Ntotal) {
    constexpr int MT = WM / 16, NT = WN / 8;
    constexpr int A_T = BM * 64;               // A tile per stage, bytes
    constexpr int B_T = BN * 64;
    constexpr int STAGE = A_T + B_T;
    constexpr int NSTAGE = 4;

    extern __shared__ __align__(16) char sm[];
    const uint32_t base = smem_u32(sm);

    const int tid = threadIdx.x, lane = tid & 31, wid = tid >> 5;
    const int m0 = blockIdx.y * BM, n0 = blockIdx.x * BN;
    constexpr int NWC = BN / WN;
    const int wm0 = (wid / NWC) * WM;
    const int wn0 = (wid % NWC) * WN;

    // per-lane z + scale (rows r, r+8 per mt quad)
    float zA[MT], zB[MT], sA[MT], sB[MT];
#pragma unroll
    for (int mt = 0; mt < MT; mt++) {
        int rA = m0 + wm0 + mt * 16 + (lane >> 2);
        zA[mt] = z[(size_t)rA * D_SZ + zcol];
        zB[mt] = z[(size_t)(rA + 8) * D_SZ + zcol];
        sA[mt] = sa[rA];
        sB[mt] = sa[rA + 8];
    }

    float acc[MT][NT][4];
#pragma unroll
    for (int mt = 0; mt < MT; mt++)
#pragma unroll
        for (int nt = 0; nt < NT; nt++)
#pragma unroll
            for (int q = 0; q < 4; q++) acc[mt][nt][q] = 0.f;

    auto produce = [&](int cc) {
        const int s = cc & (NSTAGE - 1);
        const int j = (P_SZ - 1) - cc / RCH;       // descending j
        const int rr = cc & (RCH - 1);
        const int roffA = rr * KC;
        const int koffB = j * R_SZ + rr * KC;
        const uint32_t aS = base + s * STAGE;
        const uint32_t bS = aS + A_T;
#pragma unroll
        for (int i = 0; i < (BM * 4) / THREADS; i++) {
            const int idx = tid + i * THREADS;
            const int row = idx >> 2, c16 = idx & 3;
            const uint32_t off = sw64(row, c16);
            const size_t go = (size_t)(m0 + row) * R_SZ + roffA + c16 * 8;
            CP_ASYNC16(aS + off, Aop + go);
        }
#pragma unroll
        for (int i = 0; i < (BN * 4) / THREADS; i++) {
            const int idx = tid + i * THREADS;
            const int row = idx >> 2, c16 = idx & 3;
            const uint32_t off = sw64(row, c16);
            const size_t go = (size_t)(n0 + row) * KTOT + koffB + c16 * 8;
            CP_ASYNC16(bS + off, Bop + go);
        }
        CP_COMMIT();
    };

    auto mma_chunk = [&](int s) {
        const uint32_t aS = base + s * STAGE;
        const uint32_t bS = aS + A_T;
#pragma unroll
        for (int ks = 0; ks < 2; ks++) {
            uint32_t b[NT][2];
#pragma unroll
            for (int n2 = 0; n2 < NT / 2; n2++) {
                const uint32_t rowb = wn0 + n2 * 16 + ((lane >> 4) << 3) + (lane & 7);
                const uint32_t c16b = ((lane >> 3) & 1) + 2 * ks;
                LDSM4(b[2 * n2][0], b[2 * n2][1], b[2 * n2 + 1][0], b[2 * n2 + 1][1],
                      bS + sw64(rowb, c16b));
            }
            uint32_t a[MT][4];
#pragma unroll
            for (int mt = 0; mt < MT; mt++) {
                const uint32_t rowa = wm0 + mt * 16 + (lane & 15);
                LDSM4(a[mt][0], a[mt][1], a[mt][2], a[mt][3],
                      aS + sw64(rowa, (lane >> 4) + 2 * ks));
            }
#pragma unroll
            for (int mt = 0; mt < MT; mt++)
#pragma unroll
                for (int nt = 0; nt < NT; nt++) MMA_F16(acc[mt][nt], a[mt], b[nt]);
        }
    };

    // prologue: 3 stages in flight
    produce(0); produce(1); produce(2);

    for (int c = 0; c < NCH; c++) {
        CP_WAIT2();
        __syncthreads();
        if (c + 3 < NCH) produce(c + 3); else CP_COMMIT();
        if (c && (c & (RCH - 1)) == 0) {
            // Horner: entering next-lower j — scale accumulators by z
#pragma unroll
            for (int mt = 0; mt < MT; mt++)
#pragma unroll
                for (int nt = 0; nt < NT; nt++) {
                    acc[mt][nt][0] *= zA[mt]; acc[mt][nt][1] *= zA[mt];
                    acc[mt][nt][2] *= zB[mt]; acc[mt][nt][3] *= zB[mt];
                }
        }
        mma_chunk(c & (NSTAGE - 1));
    }

    // epilogue: apply per-row scale, write f32
#pragma unroll
    for (int mt = 0; mt < MT; mt++) {
        const int row0 = m0 + wm0 + mt * 16 + (lane >> 2);
#pragma unroll
        for (int nt = 0; nt < NT; nt++) {
            const int col = n0 + wn0 + nt * 8 + (lane & 3) * 2;
            *reinterpret_cast<float2*>(&outF[(size_t)row0 * Ntotal + col]) =
                make_float2(acc[mt][nt][0] * sA[mt], acc[mt][nt][1] * sA[mt]);
            *reinterpret_cast<float2*>(&outF[(size_t)(row0 + 8) * Ntotal + col]) =
                make_float2(acc[mt][nt][2] * sB[mt], acc[mt][nt][3] * sB[mt]);
        }
    }
}

// ---------------------------------------------------------------------------
// Launch (graph-capturable, allocation-free)
// Inputs: z [B,D] f32, G0 [P,R] f32, G_mid [6,R,P,R] f32, G_last [R,P,OUT] f32, t
// Output: [B, OUT] f32
// ---------------------------------------------------------------------------
extern "C" void kernel_launch(void* const* d_in, const int* in_sizes, int n_in,
                              void* d_out, int out_size) {
    (void)in_sizes; (void)n_in; (void)out_size;
    const float* z     = (const float*)d_in[0];
    const float* G0    = (const float*)d_in[1];
    const float* Gmid  = (const float*)d_in[2];
    const float* Glast = (const float*)d_in[3];
    float* out = (float*)d_out;

    float *p_tg0, *p_resf, *p_sa;
    __half *p_qa, *p_bm, *p_bl;
    cudaGetSymbolAddress((void**)&p_tg0,  g_tanh_g0);
    cudaGetSymbolAddress((void**)&p_resf, g_resf);
    cudaGetSymbolAddress((void**)&p_sa,   g_sa);
    cudaGetSymbolAddress((void**)&p_qa,   g_qa);
    cudaGetSymbolAddress((void**)&p_bm,   g_b_mid);
    cudaGetSymbolAddress((void**)&p_bl,   g_b_last);

    // dynamic smem: 4 stages x (BM + BN) * 64 bytes
    const int SMEM_MID  = 4 * (256 + 128) * 64;  // 98304
    const int SMEM_LAST = 4 * (64 + 64) * 64;    // 32768
    cudaFuncSetAttribute((const void*)tt_mma_kernel<256, 128, 64, 32, 512>,
                         cudaFuncAttributeMaxDynamicSharedMemorySize, SMEM_MID);
    cudaFuncSetAttribute((const void*)tt_mma_kernel<64, 64, 32, 16, 256>,
                         cudaFuncAttributeMaxDynamicSharedMemorySize, SMEM_LAST);

    // precompute
    tanh_small_kernel<<<(P_SZ * R_SZ + 255) / 256, 256>>>(G0, p_tg0, P_SZ * R_SZ);
    trans_f16_kernel<<<dim3(R_SZ / 32, R_SZ / 32, NMID * P_SZ), dim3(32, 8)>>>(
        Gmid, p_bm, R_SZ, (size_t)R_SZ * P_SZ * R_SZ, (size_t)R_SZ * KTOT);
    trans_f16_kernel<<<dim3(R_SZ / 32, OUT_SZ / 32, P_SZ), dim3(32, 8)>>>(
        Glast, p_bl, OUT_SZ, 0, 0);

    // first core -> f32 res -> quantize
    first_core_kernel<<<B_SZ, R_SZ>>>(z, p_resf);
    quant_res_kernel<<<B_SZ, R_SZ>>>(p_resf, p_qa, p_sa);

    // six middle cores: GEMM (f32 out) + per-row quantize
    for (int i = 0; i < NMID; i++) {
        tt_mma_kernel<256, 128, 64, 32, 512>
            <<<dim3(R_SZ / 128, B_SZ / 256), 512, SMEM_MID>>>(
            p_qa, p_bm + (size_t)i * R_SZ * KTOT, p_sa,
            z, i + 1, p_resf, R_SZ);
        quant_res_kernel<<<B_SZ, R_SZ>>>(p_resf, p_qa, p_sa);
    }

    // last core -> d_out [B, OUT] f32
    tt_mma_kernel<64, 64, 32, 16, 256><<<dim3(1, B_SZ / 64), 256, SMEM_LAST>>>(
        p_qa, p_bl, p_sa, z, D_SZ - 1, out, OUT_SZ);
}

// round 13
// speedup vs baseline: 1.9395x; 1.1062x over previous
#include <cuda_runtime.h>
#include <cuda_fp16.h>
#include <cstdint>
#include <cstddef>

// ---------------------------------------------------------------------------
// Problem constants
// ---------------------------------------------------------------------------
#define B_SZ   8192
#define D_SZ   8
#define P_SZ   10
#define R_SZ   512
#define OUT_SZ 64
#define NMID   6
#define KTOT   (P_SZ * R_SZ)   // 5120
#define KC     32              // K per SUB-chunk
#define NCH2   (KTOT / (2 * KC))   // 80 big chunks (64 k each)

// ---------------------------------------------------------------------------
// Device-global scratch
// ---------------------------------------------------------------------------
__device__ float  g_tanh_g0[P_SZ * R_SZ];
__device__ float  g_resf[(size_t)B_SZ * R_SZ];    // f32 master res between layers
__device__ __half g_qa[(size_t)B_SZ * R_SZ];      // fp16 of res/s (per-row scaled)
__device__ float  g_sa[B_SZ];                     // per-row scale
// B operands: tanh'd, transposed to [n][k=j*512+r], single fp16 (|tanh|<=0.1)
__device__ __half g_b_mid[(size_t)NMID * R_SZ * KTOT];
__device__ __half g_b_last[(size_t)OUT_SZ * KTOT];

// ---------------------------------------------------------------------------
// PTX helpers (sm_80-era: cp.async, ldmatrix, mma.sync — NO tcgen05)
// ---------------------------------------------------------------------------
__device__ __forceinline__ uint32_t smem_u32(const void* p) {
    uint32_t a;
    asm("{ .reg .u64 t; cvta.to.shared.u64 t, %1; cvt.u32.u64 %0, t; }" : "=r"(a) : "l"(p));
    return a;
}
#define CP_ASYNC16(dst, src) \
    asm volatile("cp.async.cg.shared.global [%0], [%1], 16;" :: "r"(dst), "l"(src) : "memory")
#define CP_COMMIT() asm volatile("cp.async.commit_group;" ::: "memory")
#define CP_WAIT2()  asm volatile("cp.async.wait_group 2;" ::: "memory")

#define LDSM4(r0, r1, r2, r3, addr) \
    asm volatile("ldmatrix.sync.aligned.m8n8.x4.shared.b16 {%0,%1,%2,%3}, [%4];" \
                 : "=r"(r0), "=r"(r1), "=r"(r2), "=r"(r3) : "r"(addr))

#define MMA_F16(d, a, b) \
    asm volatile("mma.sync.aligned.m16n8k16.row.col.f32.f16.f16.f32 " \
                 "{%0,%1,%2,%3}, {%4,%5,%6,%7}, {%8,%9}, {%0,%1,%2,%3};" \
                 : "+f"((d)[0]), "+f"((d)[1]), "+f"((d)[2]), "+f"((d)[3]) \
                 : "r"((a)[0]), "r"((a)[1]), "r"((a)[2]), "r"((a)[3]), \
                   "r"((b)[0]), "r"((b)[1]))

// 64B-row XOR swizzle: conflict-free across all 8-row ldmatrix phases.
__device__ __forceinline__ uint32_t sw64(uint32_t row, uint32_t c16) {
    return row * 64u + ((c16 ^ ((row >> 1) & 3u)) << 4);
}

// ---------------------------------------------------------------------------
// Precompute: tanh + transpose -> single fp16
//   G [R, P, N] (n contiguous) -> B [n][j*512 + r] (k contiguous)
// ---------------------------------------------------------------------------
__global__ void trans_f16_kernel(const float* __restrict__ G,
                                 __half* __restrict__ bo,
                                 int N, size_t gStride, size_t oStride) {
    __shared__ float t[32][33];
    int layer = blockIdx.z / P_SZ;
    int j     = blockIdx.z % P_SZ;
    const float* Gp = G + (size_t)layer * gStride;
    __half* bop = bo + (size_t)layer * oStride;
    int rt = blockIdx.x * 32, nt = blockIdx.y * 32;
    int tx = threadIdx.x, ty = threadIdx.y;   // block (32, 8)
#pragma unroll
    for (int yy = ty; yy < 32; yy += 8)
        t[yy][tx] = tanhf(Gp[((size_t)(rt + yy) * P_SZ + j) * N + nt + tx]);
    __syncthreads();
#pragma unroll
    for (int yy = ty; yy < 32; yy += 8) {
        int n = nt + yy, r = rt + tx;
        bop[(size_t)n * KTOT + (size_t)j * R_SZ + r] = __float2half_rn(t[tx][yy]);
    }
}

__global__ void tanh_small_kernel(const float* __restrict__ src,
                                  float* __restrict__ dst, int n) {
    int i = blockIdx.x * blockDim.x + threadIdx.x;
    if (i < n) dst[i] = tanhf(src[i]);
}

// First core -> f32 res
__global__ void first_core_kernel(const float* __restrict__ z,
                                  float* __restrict__ resf) {
    int b = blockIdx.x;
    int r = threadIdx.x;
    float zv = z[b * D_SZ + 0];
    float ph = 1.f, acc = 0.f;
#pragma unroll
    for (int j = 0; j < P_SZ; j++) {
        acc += g_tanh_g0[j * R_SZ + r] * ph;
        ph *= zv;
    }
    resf[(size_t)b * R_SZ + r] = acc;
}

// Per-row quantize (vectorized): 128 threads/row, float4 loads.
//   s = rowmax |x|; A = fp16(x/s)
__global__ void quant_res_kernel(const float* __restrict__ resf,
                                 __half* __restrict__ qa,
                                 float* __restrict__ sa) {
    __shared__ float wmax[4];
    int b = blockIdx.x, tid = threadIdx.x;   // 128 threads
    float4 v = *reinterpret_cast<const float4*>(&resf[(size_t)b * R_SZ + tid * 4]);
    float a = fmaxf(fmaxf(fabsf(v.x), fabsf(v.y)), fmaxf(fabsf(v.z), fabsf(v.w)));
#pragma unroll
    for (int o = 16; o; o >>= 1) a = fmaxf(a, __shfl_xor_sync(0xffffffffu, a, o));
    if ((tid & 31) == 0) wmax[tid >> 5] = a;
    __syncthreads();
    float m = fmaxf(fmaxf(wmax[0], wmax[1]), fmaxf(wmax[2], wmax[3]));
    float s = fmaxf(m, 1e-30f);
    float inv = 1.0f / s;
    __half2 h0, h1;
    h0.x = __float2half_rn(v.x * inv); h0.y = __float2half_rn(v.y * inv);
    h1.x = __float2half_rn(v.z * inv); h1.y = __float2half_rn(v.w * inv);
    uint2 packed;
    packed.x = *reinterpret_cast<uint32_t*>(&h0);
    packed.y = *reinterpret_cast<uint32_t*>(&h1);
    *reinterpret_cast<uint2*>(&qa[(size_t)b * R_SZ + tid * 4]) = packed;
    if (tid == 0) sa[b] = s;
}

// ---------------------------------------------------------------------------
// HMMA fp16 single-pass GEMM, 64-k (2 sub-chunk) stages:
//   out[m,n] = sA[m] * sum_{j desc} ( acc*z_m + sum_r A[m,r] B_j[r,n] )
// One wait + one sync + one produce per 64 k of MMA work.
// ---------------------------------------------------------------------------
template<int BM, int BN, int WM, int WN, int THREADS>
__global__ void __launch_bounds__(THREADS, 1)
tt_mma_kernel(const __half* __restrict__ Aop,
              const __half* __restrict__ Bop,
              const float* __restrict__ sa,
              const float* __restrict__ z, int zcol,
              float* __restrict__ outF, int Ntotal) {
    constexpr int MT = WM / 16, NT = WN / 8;
    constexpr int SUB_A = BM * 64;             // A bytes per sub-chunk
    constexpr int SUB_B = BN * 64;
    constexpr int SUBT  = SUB_A + SUB_B;
    constexpr int STAGE = 2 * SUBT;            // 64-k stage
    constexpr int NSTAGE = 4;

    extern __shared__ __align__(16) char sm[];
    const uint32_t base = smem_u32(sm);

    const int tid = threadIdx.x, lane = tid & 31, wid = tid >> 5;
    const int m0 = blockIdx.y * BM, n0 = blockIdx.x * BN;
    constexpr int NWC = BN / WN;
    const int wm0 = (wid / NWC) * WM;
    const int wn0 = (wid % NWC) * WN;

    // per-lane z + scale (rows r, r+8 per mt quad)
    float zA[MT], zB[MT], sA[MT], sB[MT];
#pragma unroll
    for (int mt = 0; mt < MT; mt++) {
        int rA = m0 + wm0 + mt * 16 + (lane >> 2);
        zA[mt] = z[(size_t)rA * D_SZ + zcol];
        zB[mt] = z[(size_t)(rA + 8) * D_SZ + zcol];
        sA[mt] = sa[rA];
        sB[mt] = sa[rA + 8];
    }

    float acc[MT][NT][4];
#pragma unroll
    for (int mt = 0; mt < MT; mt++)
#pragma unroll
        for (int nt = 0; nt < NT; nt++)
#pragma unroll
            for (int q = 0; q < 4; q++) acc[mt][nt][q] = 0.f;

    // produce one 64-k stage (2 sub-chunks), one commit group
    auto produce = [&](int cc) {
        const int s = cc & (NSTAGE - 1);
        const uint32_t stg = base + s * STAGE;
#pragma unroll
        for (int sub = 0; sub < 2; sub++) {
            const int sc = 2 * cc + sub;
            const int j  = (P_SZ - 1) - (sc >> 4);   // descending j
            const int rr = sc & 15;
            const uint32_t aS = stg + sub * SUBT;
            const uint32_t bS = aS + SUB_A;
#pragma unroll
            for (int i = 0; i < (BM * 4) / THREADS; i++) {
                const int idx = tid + i * THREADS;
                const int row = idx >> 2, c16 = idx & 3;
                const uint32_t off = sw64(row, c16);
                const size_t go = (size_t)(m0 + row) * R_SZ + rr * KC + c16 * 8;
                CP_ASYNC16(aS + off, Aop + go);
            }
#pragma unroll
            for (int i = 0; i < (BN * 4) / THREADS; i++) {
                const int idx = tid + i * THREADS;
                const int row = idx >> 2, c16 = idx & 3;
                const uint32_t off = sw64(row, c16);
                const size_t go = (size_t)(n0 + row) * KTOT + j * R_SZ + rr * KC + c16 * 8;
                CP_ASYNC16(bS + off, Bop + go);
            }
        }
        CP_COMMIT();
    };

    auto mma_stage = [&](int s) {
        const uint32_t stg = base + s * STAGE;
#pragma unroll
        for (int sub = 0; sub < 2; sub++) {
            const uint32_t aS = stg + sub * SUBT;
            const uint32_t bS = aS + SUB_A;
#pragma unroll
            for (int ks = 0; ks < 2; ks++) {
                uint32_t b[NT][2];
#pragma unroll
                for (int n2 = 0; n2 < NT / 2; n2++) {
                    const uint32_t rowb = wn0 + n2 * 16 + ((lane >> 4) << 3) + (lane & 7);
                    const uint32_t c16b = ((lane >> 3) & 1) + 2 * ks;
                    LDSM4(b[2 * n2][0], b[2 * n2][1], b[2 * n2 + 1][0], b[2 * n2 + 1][1],
                          bS + sw64(rowb, c16b));
                }
                uint32_t a[MT][4];
#pragma unroll
                for (int mt = 0; mt < MT; mt++) {
                    const uint32_t rowa = wm0 + mt * 16 + (lane & 15);
                    LDSM4(a[mt][0], a[mt][1], a[mt][2], a[mt][3],
                          aS + sw64(rowa, (lane >> 4) + 2 * ks));
                }
#pragma unroll
                for (int mt = 0; mt < MT; mt++)
#pragma unroll
                    for (int nt = 0; nt < NT; nt++) MMA_F16(acc[mt][nt], a[mt], b[nt]);
            }
        }
    };

    // prologue: 3 stages in flight
    produce(0); produce(1); produce(2);

    for (int c = 0; c < NCH2; c++) {
        CP_WAIT2();
        __syncthreads();
        if (c + 3 < NCH2) produce(c + 3); else CP_COMMIT();
        if (c && (c & 7) == 0) {
            // Horner: entering next-lower j — scale accumulators by z
#pragma unroll
            for (int mt = 0; mt < MT; mt++)
#pragma unroll
                for (int nt = 0; nt < NT; nt++) {
                    acc[mt][nt][0] *= zA[mt]; acc[mt][nt][1] *= zA[mt];
                    acc[mt][nt][2] *= zB[mt]; acc[mt][nt][3] *= zB[mt];
                }
        }
        mma_stage(c & (NSTAGE - 1));
    }

    // epilogue: apply per-row scale, write f32
#pragma unroll
    for (int mt = 0; mt < MT; mt++) {
        const int row0 = m0 + wm0 + mt * 16 + (lane >> 2);
#pragma unroll
        for (int nt = 0; nt < NT; nt++) {
            const int col = n0 + wn0 + nt * 8 + (lane & 3) * 2;
            *reinterpret_cast<float2*>(&outF[(size_t)row0 * Ntotal + col]) =
                make_float2(acc[mt][nt][0] * sA[mt], acc[mt][nt][1] * sA[mt]);
            *reinterpret_cast<float2*>(&outF[(size_t)(row0 + 8) * Ntotal + col]) =
                make_float2(acc[mt][nt][2] * sB[mt], acc[mt][nt][3] * sB[mt]);
        }
    }
}

// ---------------------------------------------------------------------------
// Launch (graph-capturable, allocation-free)
// Inputs: z [B,D] f32, G0 [P,R] f32, G_mid [6,R,P,R] f32, G_last [R,P,OUT] f32, t
// Output: [B, OUT] f32
// ---------------------------------------------------------------------------
extern "C" void kernel_launch(void* const* d_in, const int* in_sizes, int n_in,
                              void* d_out, int out_size) {
    (void)in_sizes; (void)n_in; (void)out_size;
    const float* z     = (const float*)d_in[0];
    const float* G0    = (const float*)d_in[1];
    const float* Gmid  = (const float*)d_in[2];
    const float* Glast = (const float*)d_in[3];
    float* out = (float*)d_out;

    float *p_tg0, *p_resf, *p_sa;
    __half *p_qa, *p_bm, *p_bl;
    cudaGetSymbolAddress((void**)&p_tg0,  g_tanh_g0);
    cudaGetSymbolAddress((void**)&p_resf, g_resf);
    cudaGetSymbolAddress((void**)&p_sa,   g_sa);
    cudaGetSymbolAddress((void**)&p_qa,   g_qa);
    cudaGetSymbolAddress((void**)&p_bm,   g_b_mid);
    cudaGetSymbolAddress((void**)&p_bl,   g_b_last);

    // dynamic smem: 4 stages x 2 sub-chunks x (BM + BN) * 64 bytes
    const int SMEM_MID  = 4 * 2 * (256 + 128) * 64;  // 196608
    const int SMEM_LAST = 4 * 2 * (64 + 64) * 64;    // 65536
    cudaFuncSetAttribute((const void*)tt_mma_kernel<256, 128, 64, 32, 512>,
                         cudaFuncAttributeMaxDynamicSharedMemorySize, SMEM_MID);
    cudaFuncSetAttribute((const void*)tt_mma_kernel<64, 64, 32, 16, 256>,
                         cudaFuncAttributeMaxDynamicSharedMemorySize, SMEM_LAST);

    // precompute
    tanh_small_kernel<<<(P_SZ * R_SZ + 255) / 256, 256>>>(G0, p_tg0, P_SZ * R_SZ);
    trans_f16_kernel<<<dim3(R_SZ / 32, R_SZ / 32, NMID * P_SZ), dim3(32, 8)>>>(
        Gmid, p_bm, R_SZ, (size_t)R_SZ * P_SZ * R_SZ, (size_t)R_SZ * KTOT);
    trans_f16_kernel<<<dim3(R_SZ / 32, OUT_SZ / 32, P_SZ), dim3(32, 8)>>>(
        Glast, p_bl, OUT_SZ, 0, 0);

    // first core -> f32 res -> quantize
    first_core_kernel<<<B_SZ, R_SZ>>>(z, p_resf);
    quant_res_kernel<<<B_SZ, 128>>>(p_resf, p_qa, p_sa);

    // six middle cores: GEMM (f32 out) + per-row quantize
    for (int i = 0; i < NMID; i++) {
        tt_mma_kernel<256, 128, 64, 32, 512>
            <<<dim3(R_SZ / 128, B_SZ / 256), 512, SMEM_MID>>>(
            p_qa, p_bm + (size_t)i * R_SZ * KTOT, p_sa,
            z, i + 1, p_resf, R_SZ);
        quant_res_kernel<<<B_SZ, 128>>>(p_resf, p_qa, p_sa);
    }

    // last core -> d_out [B, OUT] f32
    tt_mma_kernel<64, 64, 32, 16, 256><<<dim3(1, B_SZ / 64), 256, SMEM_LAST>>>(
        p_qa, p_bl, p_sa, z, D_SZ - 1, out, OUT_SZ);
}

// round 14
// speedup vs baseline: 1.9560x; 1.0085x over previous
#include <cuda_runtime.h>
#include <cuda_fp16.h>
#include <cstdint>
#include <cstddef>

// ---------------------------------------------------------------------------
// Problem constants
// ---------------------------------------------------------------------------
#define B_SZ   8192
#define D_SZ   8
#define P_SZ   10
#define R_SZ   512
#define OUT_SZ 64
#define NMID   6
#define KTOT   (P_SZ * R_SZ)       // 5120
#define KC     32                  // K per SUB-chunk
#define NCH2   (KTOT / (2 * KC))   // 80 big chunks (64 k each)

// ---------------------------------------------------------------------------
// Device-global scratch
// ---------------------------------------------------------------------------
__device__ float  g_tanh_g0[P_SZ * R_SZ];
__device__ float  g_resf[(size_t)B_SZ * R_SZ];    // f32 master res between layers
__device__ __half g_qa[(size_t)B_SZ * R_SZ];      // fp16 of res/s (per-row scaled)
__device__ float  g_sa[B_SZ];                     // per-row scale
// B operands: tanh'd, transposed to [n][k=j*512+r], single fp16 (|tanh|<=0.1)
__device__ __half g_b_mid[(size_t)NMID * R_SZ * KTOT];
__device__ __half g_b_last[(size_t)OUT_SZ * KTOT];

// ---------------------------------------------------------------------------
// PTX helpers (sm_80-era: cp.async, ldmatrix, mma.sync — NO tcgen05)
// ---------------------------------------------------------------------------
__device__ __forceinline__ uint32_t smem_u32(const void* p) {
    uint32_t a;
    asm("{ .reg .u64 t; cvta.to.shared.u64 t, %1; cvt.u32.u64 %0, t; }" : "=r"(a) : "l"(p));
    return a;
}
#define CP_ASYNC16(dst, src) \
    asm volatile("cp.async.cg.shared.global [%0], [%1], 16;" :: "r"(dst), "l"(src) : "memory")
#define CP_COMMIT() asm volatile("cp.async.commit_group;" ::: "memory")
#define CP_WAIT1()  asm volatile("cp.async.wait_group 1;" ::: "memory")
#define CP_WAIT2()  asm volatile("cp.async.wait_group 2;" ::: "memory")

#define LDSM4(r0, r1, r2, r3, addr) \
    asm volatile("ldmatrix.sync.aligned.m8n8.x4.shared.b16 {%0,%1,%2,%3}, [%4];" \
                 : "=r"(r0), "=r"(r1), "=r"(r2), "=r"(r3) : "r"(addr))

#define MMA_F16(d, a, b) \
    asm volatile("mma.sync.aligned.m16n8k16.row.col.f32.f16.f16.f32 " \
                 "{%0,%1,%2,%3}, {%4,%5,%6,%7}, {%8,%9}, {%0,%1,%2,%3};" \
                 : "+f"((d)[0]), "+f"((d)[1]), "+f"((d)[2]), "+f"((d)[3]) \
                 : "r"((a)[0]), "r"((a)[1]), "r"((a)[2]), "r"((a)[3]), \
                   "r"((b)[0]), "r"((b)[1]))

// 64B-row XOR swizzle: conflict-free across all 8-row ldmatrix phases.
__device__ __forceinline__ uint32_t sw64(uint32_t row, uint32_t c16) {
    return row * 64u + ((c16 ^ ((row >> 1) & 3u)) << 4);
}

// ---------------------------------------------------------------------------
// Precompute: tanh + transpose -> single fp16
//   G [R, P, N] (n contiguous) -> B [n][j*512 + r] (k contiguous)
// ---------------------------------------------------------------------------
__global__ void trans_f16_kernel(const float* __restrict__ G,
                                 __half* __restrict__ bo,
                                 int N, size_t gStride, size_t oStride) {
    __shared__ float t[32][33];
    int layer = blockIdx.z / P_SZ;
    int j     = blockIdx.z % P_SZ;
    const float* Gp = G + (size_t)layer * gStride;
    __half* bop = bo + (size_t)layer * oStride;
    int rt = blockIdx.x * 32, nt = blockIdx.y * 32;
    int tx = threadIdx.x, ty = threadIdx.y;   // block (32, 8)
#pragma unroll
    for (int yy = ty; yy < 32; yy += 8)
        t[yy][tx] = tanhf(Gp[((size_t)(rt + yy) * P_SZ + j) * N + nt + tx]);
    __syncthreads();
#pragma unroll
    for (int yy = ty; yy < 32; yy += 8) {
        int n = nt + yy, r = rt + tx;
        bop[(size_t)n * KTOT + (size_t)j * R_SZ + r] = __float2half_rn(t[tx][yy]);
    }
}

__global__ void tanh_small_kernel(const float* __restrict__ src,
                                  float* __restrict__ dst, int n) {
    int i = blockIdx.x * blockDim.x + threadIdx.x;
    if (i < n) dst[i] = tanhf(src[i]);
}

// First core -> f32 res
__global__ void first_core_kernel(const float* __restrict__ z,
                                  float* __restrict__ resf) {
    int b = blockIdx.x;
    int r = threadIdx.x;
    float zv = z[b * D_SZ + 0];
    float ph = 1.f, acc = 0.f;
#pragma unroll
    for (int j = 0; j < P_SZ; j++) {
        acc += g_tanh_g0[j * R_SZ + r] * ph;
        ph *= zv;
    }
    resf[(size_t)b * R_SZ + r] = acc;
}

// Per-row quantize (vectorized): 128 threads/row, float4 loads.
//   s = rowmax |x|; A = fp16(x/s)
__global__ void quant_res_kernel(const float* __restrict__ resf,
                                 __half* __restrict__ qa,
                                 float* __restrict__ sa) {
    __shared__ float wmax[4];
    int b = blockIdx.x, tid = threadIdx.x;   // 128 threads
    float4 v = *reinterpret_cast<const float4*>(&resf[(size_t)b * R_SZ + tid * 4]);
    float a = fmaxf(fmaxf(fabsf(v.x), fabsf(v.y)), fmaxf(fabsf(v.z), fabsf(v.w)));
#pragma unroll
    for (int o = 16; o; o >>= 1) a = fmaxf(a, __shfl_xor_sync(0xffffffffu, a, o));
    if ((tid & 31) == 0) wmax[tid >> 5] = a;
    __syncthreads();
    float m = fmaxf(fmaxf(wmax[0], wmax[1]), fmaxf(wmax[2], wmax[3]));
    float s = fmaxf(m, 1e-30f);
    float inv = 1.0f / s;
    __half2 h0, h1;
    h0.x = __float2half_rn(v.x * inv); h0.y = __float2half_rn(v.y * inv);
    h1.x = __float2half_rn(v.z * inv); h1.y = __float2half_rn(v.w * inv);
    uint2 packed;
    packed.x = *reinterpret_cast<uint32_t*>(&h0);
    packed.y = *reinterpret_cast<uint32_t*>(&h1);
    *reinterpret_cast<uint2*>(&qa[(size_t)b * R_SZ + tid * 4]) = packed;
    if (tid == 0) sa[b] = s;
}

// ---------------------------------------------------------------------------
// HMMA fp16 single-pass GEMM, 64-k (2 sub-chunk) stages, Horner phi folding:
//   out[m,n] = sA[m] * sum_{j desc} ( acc*z_m + sum_r A[m,r] B_j[r,n] )
// MINCTAS CTAs co-resident per SM (independent barrier domains overlap their
// sync/wait bubbles). NSTAGE-deep cp.async ring.
// ---------------------------------------------------------------------------
template<int BM, int BN, int WM, int WN, int THREADS, int MINCTAS, int NSTAGE>
__global__ void __launch_bounds__(THREADS, MINCTAS)
tt_mma_kernel(const __half* __restrict__ Aop,
              const __half* __restrict__ Bop,
              const float* __restrict__ sa,
              const float* __restrict__ z, int zcol,
              float* __restrict__ outF, int Ntotal) {
    constexpr int MT = WM / 16, NT = WN / 8;
    constexpr int SUB_A = BM * 64;             // A bytes per sub-chunk
    constexpr int SUB_B = BN * 64;
    constexpr int SUBT  = SUB_A + SUB_B;
    constexpr int STAGE = 2 * SUBT;            // 64-k stage

    extern __shared__ __align__(16) char sm[];
    const uint32_t base = smem_u32(sm);

    const int tid = threadIdx.x, lane = tid & 31, wid = tid >> 5;
    const int m0 = blockIdx.y * BM, n0 = blockIdx.x * BN;
    constexpr int NWC = BN / WN;
    const int wm0 = (wid / NWC) * WM;
    const int wn0 = (wid % NWC) * WN;

    // per-lane z + scale (rows r, r+8 per mt quad)
    float zA[MT], zB[MT], sA[MT], sB[MT];
#pragma unroll
    for (int mt = 0; mt < MT; mt++) {
        int rA = m0 + wm0 + mt * 16 + (lane >> 2);
        zA[mt] = z[(size_t)rA * D_SZ + zcol];
        zB[mt] = z[(size_t)(rA + 8) * D_SZ + zcol];
        sA[mt] = sa[rA];
        sB[mt] = sa[rA + 8];
    }

    float acc[MT][NT][4];
#pragma unroll
    for (int mt = 0; mt < MT; mt++)
#pragma unroll
        for (int nt = 0; nt < NT; nt++)
#pragma unroll
            for (int q = 0; q < 4; q++) acc[mt][nt][q] = 0.f;

    // produce one 64-k stage (2 sub-chunks), one commit group
    auto produce = [&](int cc) {
        const int s = cc % NSTAGE;
        const uint32_t stg = base + s * STAGE;
#pragma unroll
        for (int sub = 0; sub < 2; sub++) {
            const int sc = 2 * cc + sub;
            const int j  = (P_SZ - 1) - (sc >> 4);   // descending j
            const int rr = sc & 15;
            const uint32_t aS = stg + sub * SUBT;
            const uint32_t bS = aS + SUB_A;
#pragma unroll
            for (int i = 0; i < (BM * 4) / THREADS; i++) {
                const int idx = tid + i * THREADS;
                const int row = idx >> 2, c16 = idx & 3;
                const uint32_t off = sw64(row, c16);
                const size_t go = (size_t)(m0 + row) * R_SZ + rr * KC + c16 * 8;
                CP_ASYNC16(aS + off, Aop + go);
            }
#pragma unroll
            for (int i = 0; i < (BN * 4) / THREADS; i++) {
                const int idx = tid + i * THREADS;
                const int row = idx >> 2, c16 = idx & 3;
                const uint32_t off = sw64(row, c16);
                const size_t go = (size_t)(n0 + row) * KTOT + j * R_SZ + rr * KC + c16 * 8;
                CP_ASYNC16(bS + off, Bop + go);
            }
        }
        CP_COMMIT();
    };

    auto mma_stage = [&](int s) {
        const uint32_t stg = base + s * STAGE;
#pragma unroll
        for (int sub = 0; sub < 2; sub++) {
            const uint32_t aS = stg + sub * SUBT;
            const uint32_t bS = aS + SUB_A;
#pragma unroll
            for (int ks = 0; ks < 2; ks++) {
                uint32_t b[NT][2];
#pragma unroll
                for (int n2 = 0; n2 < NT / 2; n2++) {
                    const uint32_t rowb = wn0 + n2 * 16 + ((lane >> 4) << 3) + (lane & 7);
                    const uint32_t c16b = ((lane >> 3) & 1) + 2 * ks;
                    LDSM4(b[2 * n2][0], b[2 * n2][1], b[2 * n2 + 1][0], b[2 * n2 + 1][1],
                          bS + sw64(rowb, c16b));
                }
                uint32_t a[MT][4];
#pragma unroll
                for (int mt = 0; mt < MT; mt++) {
                    const uint32_t rowa = wm0 + mt * 16 + (lane & 15);
                    LDSM4(a[mt][0], a[mt][1], a[mt][2], a[mt][3],
                          aS + sw64(rowa, (lane >> 4) + 2 * ks));
                }
#pragma unroll
                for (int mt = 0; mt < MT; mt++)
#pragma unroll
                    for (int nt = 0; nt < NT; nt++) MMA_F16(acc[mt][nt], a[mt], b[nt]);
            }
        }
    };

    // prologue: NSTAGE-1 stages in flight
#pragma unroll
    for (int p = 0; p < NSTAGE - 1; p++) produce(p);

    for (int c = 0; c < NCH2; c++) {
        if constexpr (NSTAGE == 3) CP_WAIT1(); else CP_WAIT2();
        __syncthreads();
        if (c + NSTAGE - 1 < NCH2) produce(c + NSTAGE - 1); else CP_COMMIT();
        if (c && (c & 7) == 0) {
            // Horner: entering next-lower j — scale accumulators by z
#pragma unroll
            for (int mt = 0; mt < MT; mt++)
#pragma unroll
                for (int nt = 0; nt < NT; nt++) {
                    acc[mt][nt][0] *= zA[mt]; acc[mt][nt][1] *= zA[mt];
                    acc[mt][nt][2] *= zB[mt]; acc[mt][nt][3] *= zB[mt];
                }
        }
        mma_stage(c % NSTAGE);
    }

    // epilogue: apply per-row scale, write f32
#pragma unroll
    for (int mt = 0; mt < MT; mt++) {
        const int row0 = m0 + wm0 + mt * 16 + (lane >> 2);
#pragma unroll
        for (int nt = 0; nt < NT; nt++) {
            const int col = n0 + wn0 + nt * 8 + (lane & 3) * 2;
            *reinterpret_cast<float2*>(&outF[(size_t)row0 * Ntotal + col]) =
                make_float2(acc[mt][nt][0] * sA[mt], acc[mt][nt][1] * sA[mt]);
            *reinterpret_cast<float2*>(&outF[(size_t)(row0 + 8) * Ntotal + col]) =
                make_float2(acc[mt][nt][2] * sB[mt], acc[mt][nt][3] * sB[mt]);
        }
    }
}

// ---------------------------------------------------------------------------
// Launch (graph-capturable, allocation-free)
// Inputs: z [B,D] f32, G0 [P,R] f32, G_mid [6,R,P,R] f32, G_last [R,P,OUT] f32, t
// Output: [B, OUT] f32
// ---------------------------------------------------------------------------
extern "C" void kernel_launch(void* const* d_in, const int* in_sizes, int n_in,
                              void* d_out, int out_size) {
    (void)in_sizes; (void)n_in; (void)out_size;
    const float* z     = (const float*)d_in[0];
    const float* G0    = (const float*)d_in[1];
    const float* Gmid  = (const float*)d_in[2];
    const float* Glast = (const float*)d_in[3];
    float* out = (float*)d_out;

    float *p_tg0, *p_resf, *p_sa;
    __half *p_qa, *p_bm, *p_bl;
    cudaGetSymbolAddress((void**)&p_tg0,  g_tanh_g0);
    cudaGetSymbolAddress((void**)&p_resf, g_resf);
    cudaGetSymbolAddress((void**)&p_sa,   g_sa);
    cudaGetSymbolAddress((void**)&p_qa,   g_qa);
    cudaGetSymbolAddress((void**)&p_bm,   g_b_mid);
    cudaGetSymbolAddress((void**)&p_bl,   g_b_last);

    // mids: 3 stages x 2 subs x (128+128)*64 = 98304 B/CTA -> 2 CTAs/SM
    const int SMEM_MID  = 3 * 2 * (128 + 128) * 64;  // 98304
    const int SMEM_LAST = 4 * 2 * (64 + 64) * 64;    // 65536
    cudaFuncSetAttribute((const void*)tt_mma_kernel<128, 128, 64, 32, 256, 2, 3>,
                         cudaFuncAttributeMaxDynamicSharedMemorySize, SMEM_MID);
    cudaFuncSetAttribute((const void*)tt_mma_kernel<64, 64, 32, 16, 256, 1, 4>,
                         cudaFuncAttributeMaxDynamicSharedMemorySize, SMEM_LAST);

    // precompute
    tanh_small_kernel<<<(P_SZ * R_SZ + 255) / 256, 256>>>(G0, p_tg0, P_SZ * R_SZ);
    trans_f16_kernel<<<dim3(R_SZ / 32, R_SZ / 32, NMID * P_SZ), dim3(32, 8)>>>(
        Gmid, p_bm, R_SZ, (size_t)R_SZ * P_SZ * R_SZ, (size_t)R_SZ * KTOT);
    trans_f16_kernel<<<dim3(R_SZ / 32, OUT_SZ / 32, P_SZ), dim3(32, 8)>>>(
        Glast, p_bl, OUT_SZ, 0, 0);

    // first core -> f32 res -> quantize
    first_core_kernel<<<B_SZ, R_SZ>>>(z, p_resf);
    quant_res_kernel<<<B_SZ, 128>>>(p_resf, p_qa, p_sa);

    // six middle cores: GEMM (f32 out) + per-row quantize — 256 CTAs, 2/SM
    for (int i = 0; i < NMID; i++) {
        tt_mma_kernel<128, 128, 64, 32, 256, 2, 3>
            <<<dim3(R_SZ / 128, B_SZ / 128), 256, SMEM_MID>>>(
            p_qa, p_bm + (size_t)i * R_SZ * KTOT, p_sa,
            z, i + 1, p_resf, R_SZ);
        quant_res_kernel<<<B_SZ, 128>>>(p_resf, p_qa, p_sa);
    }

    // last core -> d_out [B, OUT] f32
    tt_mma_kernel<64, 64, 32, 16, 256, 1, 4><<<dim3(1, B_SZ / 64), 256, SMEM_LAST>>>(
        p_qa, p_bl, p_sa, z, D_SZ - 1, out, OUT_SZ);
}